// round 1
// baseline (speedup 1.0000x reference)
#include <cuda_runtime.h>

// Problem constants
constexpr int kB  = 2;
constexpr int kS  = 2048;
constexpr int kH  = 512;
constexpr int kNH = 8;
constexpr int kDK = 64;
constexpr int kM  = kB * kS;       // 4096 rows for all projections
constexpr float kScale = 0.125f;   // 1/sqrt(64)

// Scratch (device globals; no allocations allowed)
__device__ float g_qh[kB * kNH * kS * kDK];   // [B,NH,S,DK], pre-scaled by kScale
__device__ float g_kh[kB * kNH * kS * kDK];
__device__ float g_vh[kB * kNH * kS * kDK];
__device__ float g_ctx[kM * kH];              // [B*S, H]

// ---------------------------------------------------------------------------
// Register-tiled GEMM: Y[M,N] = X[M,K] @ W[K,N] + bias
// BM=BN=64, BK=16, 256 threads, 4x4 per thread.
// mode 0/1/2: out -> g_qh/g_kh/g_vh in head layout ([B,NH,S,DK]); mode 0 scales.
// mode 3:     X = g_ctx, out -> Yout plain row-major [M,H].
// ---------------------------------------------------------------------------
__global__ __launch_bounds__(256) void gemm_kernel(
    const float* __restrict__ X, const float* __restrict__ W,
    const float* __restrict__ bias, float* __restrict__ Yout, int mode)
{
    __shared__ float As[16][64];   // [k][m] (transposed store)
    __shared__ float Bs[16][64];   // [k][n]

    const float* Xp = (mode == 3) ? g_ctx : X;
    float* out = (mode == 0) ? g_qh : (mode == 1) ? g_kh
               : (mode == 2) ? g_vh : Yout;

    const int tid = threadIdx.x;
    const int ty = tid >> 4, tx = tid & 15;
    const int m0 = blockIdx.y << 6, n0 = blockIdx.x << 6;

    float acc[4][4];
#pragma unroll
    for (int i = 0; i < 4; i++)
#pragma unroll
        for (int j = 0; j < 4; j++) acc[i][j] = 0.f;

    const int ar = tid >> 2, ac4 = (tid & 3) << 2;   // A tile: 64 rows x 16 k
    const int br = tid >> 4, bc4 = (tid & 15) << 2;  // B tile: 16 k x 64 n

    for (int k0 = 0; k0 < kH; k0 += 16) {
        float4 av = *(const float4*)&Xp[(size_t)(m0 + ar) * kH + k0 + ac4];
        float4 bv = *(const float4*)&W [(size_t)(k0 + br) * kH + n0 + bc4];
        __syncthreads();
        As[ac4 + 0][ar] = av.x;
        As[ac4 + 1][ar] = av.y;
        As[ac4 + 2][ar] = av.z;
        As[ac4 + 3][ar] = av.w;
        *(float4*)&Bs[br][bc4] = bv;
        __syncthreads();
#pragma unroll
        for (int kk = 0; kk < 16; ++kk) {
            float4 a = *(const float4*)&As[kk][ty << 2];
            float4 b = *(const float4*)&Bs[kk][tx << 2];
            float aa[4] = {a.x, a.y, a.z, a.w};
            float bb[4] = {b.x, b.y, b.z, b.w};
#pragma unroll
            for (int i = 0; i < 4; i++)
#pragma unroll
                for (int j = 0; j < 4; j++)
                    acc[i][j] = fmaf(aa[i], bb[j], acc[i][j]);
        }
    }

    const int nbase = n0 + (tx << 2);
    float4 bvec = *(const float4*)&bias[nbase];
    float bb[4] = {bvec.x, bvec.y, bvec.z, bvec.w};

#pragma unroll
    for (int i = 0; i < 4; i++) {
        const int m = m0 + (ty << 2) + i;
        float vv[4];
#pragma unroll
        for (int j = 0; j < 4; j++) {
            float val = acc[i][j] + bb[j];
            if (mode == 0) val *= kScale;
            vv[j] = val;
        }
        float4 v4 = make_float4(vv[0], vv[1], vv[2], vv[3]);
        if (mode < 3) {
            const int b_ = m >> 11;               // /kS
            const int s_ = m & (kS - 1);
            const int h_ = nbase >> 6;            // /kDK
            const int d_ = nbase & (kDK - 1);
            *(float4*)&out[(((size_t)(b_ * kNH + h_)) * kS + s_) * kDK + d_] = v4;
        } else {
            *(float4*)&out[(size_t)m * kH + nbase] = v4;
        }
    }
}

// ---------------------------------------------------------------------------
// Flash attention with additive bias.
// Grid: (S/64 q-tiles, B*NH). 256 threads: ty=row-group (4 rows), tx=col-group
// (4 cols). Q pre-scaled. Online softmax, P via smem, ctx accumulated in regs.
// Dynamic smem: Qst[64][64] (d-major) + Kst[64][64] (d-major) + Vs[64][64]
//               + Ps[64][65]  = 65792 bytes.
// ---------------------------------------------------------------------------
__global__ __launch_bounds__(256) void attn_kernel(const float* __restrict__ bias)
{
    extern __shared__ float sm[];
    float* Qst = sm;            // [d][r]
    float* Kst = sm + 4096;     // [d][c]
    float* Vs  = sm + 8192;     // [kv][dk]
    float* Ps  = sm + 12288;    // [r][65]

    const int bh = blockIdx.y;
    const int q0 = blockIdx.x << 6;
    const float* Qg = g_qh + (size_t)bh * kS * kDK;
    const float* Kg = g_kh + (size_t)bh * kS * kDK;
    const float* Vg = g_vh + (size_t)bh * kS * kDK;
    const float* Bp = bias + (size_t)bh * kS * kS;

    const int tid = threadIdx.x;
    const int ty = tid >> 4, tx = tid & 15;
    const int r0 = ty << 2, c0 = tx << 2;

    // Load Q tile, transposed into smem
    {
        const int r = tid >> 2, d4 = (tid & 3) << 4;
#pragma unroll
        for (int u = 0; u < 4; ++u) {
            const int d = d4 + (u << 2);
            float4 q4 = *(const float4*)&Qg[(size_t)(q0 + r) * kDK + d];
            Qst[(d + 0) * 64 + r] = q4.x;
            Qst[(d + 1) * 64 + r] = q4.y;
            Qst[(d + 2) * 64 + r] = q4.z;
            Qst[(d + 3) * 64 + r] = q4.w;
        }
    }

    float m_[4], l_[4], O[4][4];
#pragma unroll
    for (int i = 0; i < 4; i++) {
        m_[i] = -1e30f;
        l_[i] = 0.f;
#pragma unroll
        for (int j = 0; j < 4; j++) O[i][j] = 0.f;
    }

    const int cr = tid >> 2, d4 = (tid & 3) << 4;

    for (int t = 0; t < kS / 64; ++t) {
        const int k0 = t << 6;

        // Prefetch K/V tile from global
        float4 kv4[4], vv4[4];
#pragma unroll
        for (int u = 0; u < 4; ++u) {
            const int d = d4 + (u << 2);
            kv4[u] = *(const float4*)&Kg[(size_t)(k0 + cr) * kDK + d];
            vv4[u] = *(const float4*)&Vg[(size_t)(k0 + cr) * kDK + d];
        }
        __syncthreads();   // previous iteration's smem reads complete
#pragma unroll
        for (int u = 0; u < 4; ++u) {
            const int d = d4 + (u << 2);
            Kst[(d + 0) * 64 + cr] = kv4[u].x;
            Kst[(d + 1) * 64 + cr] = kv4[u].y;
            Kst[(d + 2) * 64 + cr] = kv4[u].z;
            Kst[(d + 3) * 64 + cr] = kv4[u].w;
            *(float4*)&Vs[cr * 64 + d] = vv4[u];
        }
        __syncthreads();

        // scores = Q @ K^T (Q pre-scaled)
        float acc[4][4];
#pragma unroll
        for (int i = 0; i < 4; i++)
#pragma unroll
            for (int j = 0; j < 4; j++) acc[i][j] = 0.f;

#pragma unroll 8
        for (int d = 0; d < 64; ++d) {
            float4 a = *(const float4*)&Qst[d * 64 + r0];
            float4 b = *(const float4*)&Kst[d * 64 + c0];
            float aa[4] = {a.x, a.y, a.z, a.w};
            float bb[4] = {b.x, b.y, b.z, b.w};
#pragma unroll
            for (int i = 0; i < 4; i++)
#pragma unroll
                for (int j = 0; j < 4; j++)
                    acc[i][j] = fmaf(aa[i], bb[j], acc[i][j]);
        }

        // add bias tile
#pragma unroll
        for (int i = 0; i < 4; ++i) {
            float4 bb = *(const float4*)&Bp[(size_t)(q0 + r0 + i) * kS + k0 + c0];
            acc[i][0] += bb.x; acc[i][1] += bb.y;
            acc[i][2] += bb.z; acc[i][3] += bb.w;
        }

        // online softmax
        float rm[4], rs[4], al[4];
#pragma unroll
        for (int i = 0; i < 4; ++i)
            rm[i] = fmaxf(fmaxf(acc[i][0], acc[i][1]), fmaxf(acc[i][2], acc[i][3]));
#pragma unroll
        for (int off = 1; off < 16; off <<= 1)
#pragma unroll
            for (int i = 0; i < 4; ++i)
                rm[i] = fmaxf(rm[i], __shfl_xor_sync(0xffffffffu, rm[i], off));

#pragma unroll
        for (int i = 0; i < 4; ++i) {
            float mn = fmaxf(m_[i], rm[i]);
            al[i] = __expf(m_[i] - mn);
            m_[i] = mn;
            float s = 0.f;
#pragma unroll
            for (int j = 0; j < 4; ++j) {
                float p = __expf(acc[i][j] - mn);
                Ps[(r0 + i) * 65 + c0 + j] = p;
                s += p;
            }
            rs[i] = s;
        }
#pragma unroll
        for (int off = 1; off < 16; off <<= 1)
#pragma unroll
            for (int i = 0; i < 4; ++i)
                rs[i] += __shfl_xor_sync(0xffffffffu, rs[i], off);
#pragma unroll
        for (int i = 0; i < 4; ++i) {
            l_[i] = l_[i] * al[i] + rs[i];
#pragma unroll
            for (int j = 0; j < 4; ++j) O[i][j] *= al[i];
        }

        __syncwarp();   // Ps rows are produced/consumed within the same warp

        // ctx += P @ V
#pragma unroll 8
        for (int kv = 0; kv < 64; ++kv) {
            float4 v4 = *(const float4*)&Vs[kv * 64 + c0];
            float vb[4] = {v4.x, v4.y, v4.z, v4.w};
#pragma unroll
            for (int i = 0; i < 4; ++i) {
                float p = Ps[(r0 + i) * 65 + kv];
#pragma unroll
                for (int j = 0; j < 4; ++j)
                    O[i][j] = fmaf(p, vb[j], O[i][j]);
            }
        }
    }

    // epilogue: normalize, write to [B*S, H] layout for the output GEMM
    const int b_ = bh / kNH, h_ = bh % kNH;
#pragma unroll
    for (int i = 0; i < 4; ++i) {
        float inv = 1.f / l_[i];
        float4 o4 = make_float4(O[i][0] * inv, O[i][1] * inv,
                                O[i][2] * inv, O[i][3] * inv);
        *(float4*)&g_ctx[(size_t)(b_ * kS + q0 + r0 + i) * kH + h_ * kDK + c0] = o4;
    }
}

// ---------------------------------------------------------------------------
extern "C" void kernel_launch(void* const* d_in, const int* in_sizes, int n_in,
                              void* d_out, int out_size)
{
    const float* q  = (const float*)d_in[0];
    const float* k  = (const float*)d_in[1];
    const float* v  = (const float*)d_in[2];
    const float* ab = (const float*)d_in[3];
    const float* Wq = (const float*)d_in[4];
    const float* bq = (const float*)d_in[5];
    const float* Wk = (const float*)d_in[6];
    const float* bk = (const float*)d_in[7];
    const float* Wv = (const float*)d_in[8];
    const float* bv = (const float*)d_in[9];
    const float* Wo = (const float*)d_in[10];
    const float* bo = (const float*)d_in[11];
    float* out = (float*)d_out;

    const int attn_smem = 65792;  // (3*4096 + 64*65) * 4 bytes
    cudaFuncSetAttribute(attn_kernel,
                         cudaFuncAttributeMaxDynamicSharedMemorySize, attn_smem);

    dim3 blk(256);
    dim3 ggrid(kH / 64, kM / 64);          // (8, 64)

    gemm_kernel<<<ggrid, blk>>>(q, Wq, bq, nullptr, 0);
    gemm_kernel<<<ggrid, blk>>>(k, Wk, bk, nullptr, 1);
    gemm_kernel<<<ggrid, blk>>>(v, Wv, bv, nullptr, 2);

    attn_kernel<<<dim3(kS / 64, kB * kNH), blk, attn_smem>>>(ab);

    gemm_kernel<<<ggrid, blk>>>(nullptr, Wo, bo, out, 3);
}

// round 2
// speedup vs baseline: 1.7883x; 1.7883x over previous
#include <cuda_runtime.h>
#include <cuda_bf16.h>
#include <cstdint>

// Problem constants
constexpr int kB  = 2;
constexpr int kS  = 2048;
constexpr int kH  = 512;
constexpr int kNH = 8;
constexpr int kDK = 64;
constexpr int kM  = kB * kS;       // 4096
constexpr float kScale = 0.125f;   // 1/sqrt(64)

constexpr int kHE = kB * kNH * kS * kDK;  // elems per head tensor (2M)

// Scratch (device globals; no allocations allowed)
__device__ __nv_bfloat16 g_qhi[kHE], g_qlo[kHE];
__device__ __nv_bfloat16 g_khi[kHE], g_klo[kHE];
__device__ __nv_bfloat16 g_vhi[kHE], g_vlo[kHE];
__device__ float g_ctx[kM * kH];          // [B*S, H]

// ---------------------------------------------------------------------------
// Register-tiled fp32 GEMM: Y[M,N] = X[M,K] @ W[K,N] + bias
// mode 0/1/2: out -> q/k/v hi+lo bf16 pairs in head layout [B,NH,S,DK]
//             (mode 0 applies kScale). mode 3: X = g_ctx, plain fp32 out.
// ---------------------------------------------------------------------------
__global__ __launch_bounds__(256) void gemm_kernel(
    const float* __restrict__ X, const float* __restrict__ W,
    const float* __restrict__ bias, float* __restrict__ Yout, int mode)
{
    __shared__ float As[16][64];
    __shared__ float Bs[16][64];

    const float* Xp = (mode == 3) ? g_ctx : X;

    const int tid = threadIdx.x;
    const int ty = tid >> 4, tx = tid & 15;
    const int m0 = blockIdx.y << 6, n0 = blockIdx.x << 6;

    float acc[4][4];
#pragma unroll
    for (int i = 0; i < 4; i++)
#pragma unroll
        for (int j = 0; j < 4; j++) acc[i][j] = 0.f;

    const int ar = tid >> 2, ac4 = (tid & 3) << 2;
    const int br = tid >> 4, bc4 = (tid & 15) << 2;

    for (int k0 = 0; k0 < kH; k0 += 16) {
        float4 av = *(const float4*)&Xp[(size_t)(m0 + ar) * kH + k0 + ac4];
        float4 bv = *(const float4*)&W [(size_t)(k0 + br) * kH + n0 + bc4];
        __syncthreads();
        As[ac4 + 0][ar] = av.x;
        As[ac4 + 1][ar] = av.y;
        As[ac4 + 2][ar] = av.z;
        As[ac4 + 3][ar] = av.w;
        *(float4*)&Bs[br][bc4] = bv;
        __syncthreads();
#pragma unroll
        for (int kk = 0; kk < 16; ++kk) {
            float4 a = *(const float4*)&As[kk][ty << 2];
            float4 b = *(const float4*)&Bs[kk][tx << 2];
            float aa[4] = {a.x, a.y, a.z, a.w};
            float bb[4] = {b.x, b.y, b.z, b.w};
#pragma unroll
            for (int i = 0; i < 4; i++)
#pragma unroll
                for (int j = 0; j < 4; j++)
                    acc[i][j] = fmaf(aa[i], bb[j], acc[i][j]);
        }
    }

    const int nbase = n0 + (tx << 2);
    float4 bvec = *(const float4*)&bias[nbase];
    float bb[4] = {bvec.x, bvec.y, bvec.z, bvec.w};

    __nv_bfloat16* oh = (mode == 0) ? g_qhi : (mode == 1) ? g_khi : g_vhi;
    __nv_bfloat16* ol = (mode == 0) ? g_qlo : (mode == 1) ? g_klo : g_vlo;

#pragma unroll
    for (int i = 0; i < 4; i++) {
        const int m = m0 + (ty << 2) + i;
        float vv[4];
#pragma unroll
        for (int j = 0; j < 4; j++) {
            float val = acc[i][j] + bb[j];
            if (mode == 0) val *= kScale;
            vv[j] = val;
        }
        if (mode < 3) {
            const int b_ = m >> 11;
            const int s_ = m & (kS - 1);
            const int h_ = nbase >> 6;
            const int d_ = nbase & (kDK - 1);
            size_t off = (((size_t)(b_ * kNH + h_)) * kS + s_) * kDK + d_;
            __nv_bfloat162 h01 = __floats2bfloat162_rn(vv[0], vv[1]);
            __nv_bfloat162 h23 = __floats2bfloat162_rn(vv[2], vv[3]);
            *(__nv_bfloat162*)&oh[off + 0] = h01;
            *(__nv_bfloat162*)&oh[off + 2] = h23;
            __nv_bfloat162 l01 = __floats2bfloat162_rn(vv[0] - __low2float(h01),
                                                       vv[1] - __high2float(h01));
            __nv_bfloat162 l23 = __floats2bfloat162_rn(vv[2] - __low2float(h23),
                                                       vv[3] - __high2float(h23));
            *(__nv_bfloat162*)&ol[off + 0] = l01;
            *(__nv_bfloat162*)&ol[off + 2] = l23;
        } else {
            *(float4*)&Yout[(size_t)m * kH + nbase] =
                make_float4(vv[0], vv[1], vv[2], vv[3]);
        }
    }
}

// ---------------------------------------------------------------------------
// Tensor-core flash attention (mma.sync bf16, hi/lo split = 3 MMAs per matmul)
// CTA: 128 q rows of one (b,h). 8 warps x 16 rows. kv tiles of 128.
// ---------------------------------------------------------------------------
constexpr int kQStr = 72;   // bf16 elems per smem row (conflict-free ldmatrix)

__device__ __forceinline__ uint32_t smaddr(const void* p) {
    return (uint32_t)__cvta_generic_to_shared(p);
}
__device__ __forceinline__ void ldsm_x4(uint32_t* r, uint32_t a) {
    asm volatile("ldmatrix.sync.aligned.m8n8.x4.shared.b16 {%0,%1,%2,%3},[%4];"
        : "=r"(r[0]), "=r"(r[1]), "=r"(r[2]), "=r"(r[3]) : "r"(a));
}
__device__ __forceinline__ void ldsm_x2(uint32_t* r, uint32_t a) {
    asm volatile("ldmatrix.sync.aligned.m8n8.x2.shared.b16 {%0,%1},[%2];"
        : "=r"(r[0]), "=r"(r[1]) : "r"(a));
}
__device__ __forceinline__ void ldsm_x2t(uint32_t* r, uint32_t a) {
    asm volatile("ldmatrix.sync.aligned.m8n8.x2.trans.shared.b16 {%0,%1},[%2];"
        : "=r"(r[0]), "=r"(r[1]) : "r"(a));
}
__device__ __forceinline__ void mma_bf16(float* c, const uint32_t* a,
                                         const uint32_t* b) {
    asm volatile(
        "mma.sync.aligned.m16n8k16.row.col.f32.bf16.bf16.f32 "
        "{%0,%1,%2,%3},{%4,%5,%6,%7},{%8,%9},{%0,%1,%2,%3};"
        : "+f"(c[0]), "+f"(c[1]), "+f"(c[2]), "+f"(c[3])
        : "r"(a[0]), "r"(a[1]), "r"(a[2]), "r"(a[3]), "r"(b[0]), "r"(b[1]));
}
__device__ __forceinline__ uint32_t pack_bf16(float x, float y) {
    __nv_bfloat162 h = __floats2bfloat162_rn(x, y);
    return *reinterpret_cast<uint32_t*>(&h);
}

__global__ __launch_bounds__(256, 1) void attn_kernel(const float* __restrict__ bias)
{
    extern __shared__ __nv_bfloat16 sm[];
    __nv_bfloat16* Qh = sm;                    // [128][72]
    __nv_bfloat16* Ql = Qh + 128 * kQStr;
    __nv_bfloat16* Kh = Ql + 128 * kQStr;
    __nv_bfloat16* Kl = Kh + 128 * kQStr;
    __nv_bfloat16* Vh = Kl + 128 * kQStr;
    __nv_bfloat16* Vl = Vh + 128 * kQStr;

    const int bh = blockIdx.y;
    const int q0 = blockIdx.x << 7;
    const int tid = threadIdx.x;
    const int lane = tid & 31, w = tid >> 5;

    const size_t hb = (size_t)bh * kS * kDK;
    const __nv_bfloat16* Qgh = g_qhi + hb;
    const __nv_bfloat16* Qgl = g_qlo + hb;
    const __nv_bfloat16* Kgh = g_khi + hb;
    const __nv_bfloat16* Kgl = g_klo + hb;
    const __nv_bfloat16* Vgh = g_vhi + hb;
    const __nv_bfloat16* Vgl = g_vlo + hb;
    const float* Bp = bias + (size_t)bh * kS * kS + (size_t)q0 * kS;

    // Load Q tile (128 x 64 bf16 hi/lo)
    {
        const int r = tid >> 3, c8 = (tid & 7) << 3;
#pragma unroll
        for (int u = 0; u < 4; ++u) {
            const int row = r + (u << 5);
            *(uint4*)&Qh[row * kQStr + c8] =
                *(const uint4*)&Qgh[(size_t)(q0 + row) * kDK + c8];
            *(uint4*)&Ql[row * kQStr + c8] =
                *(const uint4*)&Qgl[(size_t)(q0 + row) * kDK + c8];
        }
    }
    __syncthreads();

    // Q fragments, resident for whole kernel
    uint32_t qfh[4][4], qfl[4][4];
    {
        const int r0 = w << 4;
#pragma unroll
        for (int kc = 0; kc < 4; ++kc) {
            const int row = r0 + (lane & 15);
            const int col = (kc << 4) + ((lane >> 4) << 3);
            ldsm_x4(qfh[kc], smaddr(&Qh[row * kQStr + col]));
            ldsm_x4(qfl[kc], smaddr(&Ql[row * kQStr + col]));
        }
    }

    float O[8][4];
#pragma unroll
    for (int j = 0; j < 8; j++)
#pragma unroll
        for (int i = 0; i < 4; i++) O[j][i] = 0.f;
    float m0 = -1e30f, m1 = -1e30f, l0 = 0.f, l1 = 0.f;

    const int rq = lane >> 2;          // row within 16-row warp tile
    const int cq = (lane & 3) << 1;    // col pair within n8 tile

    for (int t = 0; t < kS / 128; ++t) {
        const int k0 = t << 7;
        __syncthreads();
        // load K/V tile (hi/lo)
        {
            const int r = tid >> 3, c8 = (tid & 7) << 3;
#pragma unroll
            for (int u = 0; u < 4; ++u) {
                const int row = r + (u << 5);
                const size_t g = (size_t)(k0 + row) * kDK + c8;
                *(uint4*)&Kh[row * kQStr + c8] = *(const uint4*)&Kgh[g];
                *(uint4*)&Kl[row * kQStr + c8] = *(const uint4*)&Kgl[g];
                *(uint4*)&Vh[row * kQStr + c8] = *(const uint4*)&Vgh[g];
                *(uint4*)&Vl[row * kQStr + c8] = *(const uint4*)&Vgl[g];
            }
        }
        __syncthreads();

        // scores: acc = Qhi Khi + Qlo Khi + Qhi Klo (+ bias)
        float acc[16][4];
#pragma unroll
        for (int j = 0; j < 16; ++j) {
            acc[j][0] = acc[j][1] = acc[j][2] = acc[j][3] = 0.f;
#pragma unroll
            for (int kc = 0; kc < 4; ++kc) {
                const int row = (j << 3) + (lane & 7);
                const int col = (kc << 4) + (((lane >> 3) & 1) << 3);
                uint32_t kb[2], kbl[2];
                ldsm_x2(kb, smaddr(&Kh[row * kQStr + col]));
                mma_bf16(acc[j], qfh[kc], kb);
                mma_bf16(acc[j], qfl[kc], kb);
                ldsm_x2(kbl, smaddr(&Kl[row * kQStr + col]));
                mma_bf16(acc[j], qfh[kc], kbl);
            }
            const float* bp = Bp + (size_t)((w << 4) + rq) * kS + k0 + (j << 3) + cq;
            float2 bA = *(const float2*)bp;
            float2 bB = *(const float2*)(bp + 8 * (size_t)kS);
            acc[j][0] += bA.x; acc[j][1] += bA.y;
            acc[j][2] += bB.x; acc[j][3] += bB.y;
        }

        // online softmax on fragments
        float mx0 = -1e30f, mx1 = -1e30f;
#pragma unroll
        for (int j = 0; j < 16; ++j) {
            mx0 = fmaxf(mx0, fmaxf(acc[j][0], acc[j][1]));
            mx1 = fmaxf(mx1, fmaxf(acc[j][2], acc[j][3]));
        }
        mx0 = fmaxf(mx0, __shfl_xor_sync(0xffffffffu, mx0, 1));
        mx0 = fmaxf(mx0, __shfl_xor_sync(0xffffffffu, mx0, 2));
        mx1 = fmaxf(mx1, __shfl_xor_sync(0xffffffffu, mx1, 1));
        mx1 = fmaxf(mx1, __shfl_xor_sync(0xffffffffu, mx1, 2));

        const float mn0 = fmaxf(m0, mx0), mn1 = fmaxf(m1, mx1);
        const float a0 = __expf(m0 - mn0), a1 = __expf(m1 - mn1);
        m0 = mn0; m1 = mn1;
        l0 *= a0;  l1 *= a1;
#pragma unroll
        for (int jn = 0; jn < 8; ++jn) {
            O[jn][0] *= a0; O[jn][1] *= a0;
            O[jn][2] *= a1; O[jn][3] *= a1;
        }

        uint32_t Ph[8][4], Pl[8][4];
#pragma unroll
        for (int j = 0; j < 16; ++j) {
            float p0 = __expf(acc[j][0] - mn0);
            float p1 = __expf(acc[j][1] - mn0);
            float p2 = __expf(acc[j][2] - mn1);
            float p3 = __expf(acc[j][3] - mn1);
            l0 += p0 + p1;
            l1 += p2 + p3;
            const int kc = j >> 1, bofs = (j & 1) << 1;
            __nv_bfloat162 h01 = __floats2bfloat162_rn(p0, p1);
            __nv_bfloat162 h23 = __floats2bfloat162_rn(p2, p3);
            Ph[kc][bofs]     = *reinterpret_cast<uint32_t*>(&h01);
            Ph[kc][bofs + 1] = *reinterpret_cast<uint32_t*>(&h23);
            Pl[kc][bofs]     = pack_bf16(p0 - __low2float(h01), p1 - __high2float(h01));
            Pl[kc][bofs + 1] = pack_bf16(p2 - __low2float(h23), p3 - __high2float(h23));
        }

        // O += P @ V  (Phi Vhi + Plo Vhi + Phi Vlo)
#pragma unroll
        for (int jn = 0; jn < 8; ++jn) {
#pragma unroll
            for (int kc = 0; kc < 8; ++kc) {
                const int row = (kc << 4) + (lane & 15);
                const int col = jn << 3;
                uint32_t vb[2], vbl[2];
                ldsm_x2t(vb, smaddr(&Vh[row * kQStr + col]));
                mma_bf16(O[jn], Ph[kc], vb);
                mma_bf16(O[jn], Pl[kc], vb);
                ldsm_x2t(vbl, smaddr(&Vl[row * kQStr + col]));
                mma_bf16(O[jn], Ph[kc], vbl);
            }
        }
    }

    // epilogue
    l0 += __shfl_xor_sync(0xffffffffu, l0, 1);
    l0 += __shfl_xor_sync(0xffffffffu, l0, 2);
    l1 += __shfl_xor_sync(0xffffffffu, l1, 1);
    l1 += __shfl_xor_sync(0xffffffffu, l1, 2);
    const float inv0 = 1.f / l0, inv1 = 1.f / l1;

    const int b_ = bh >> 3, h_ = bh & 7;
    const int grow = q0 + (w << 4) + rq;
    float* cp = g_ctx + ((size_t)b_ * kS + grow) * kH + h_ * kDK + cq;
#pragma unroll
    for (int jn = 0; jn < 8; ++jn) {
        *(float2*)(cp + (jn << 3)) =
            make_float2(O[jn][0] * inv0, O[jn][1] * inv0);
        *(float2*)(cp + (jn << 3) + 8 * kH) =
            make_float2(O[jn][2] * inv1, O[jn][3] * inv1);
    }
}

// ---------------------------------------------------------------------------
extern "C" void kernel_launch(void* const* d_in, const int* in_sizes, int n_in,
                              void* d_out, int out_size)
{
    const float* q  = (const float*)d_in[0];
    const float* k  = (const float*)d_in[1];
    const float* v  = (const float*)d_in[2];
    const float* ab = (const float*)d_in[3];
    const float* Wq = (const float*)d_in[4];
    const float* bq = (const float*)d_in[5];
    const float* Wk = (const float*)d_in[6];
    const float* bk = (const float*)d_in[7];
    const float* Wv = (const float*)d_in[8];
    const float* bv = (const float*)d_in[9];
    const float* Wo = (const float*)d_in[10];
    const float* bo = (const float*)d_in[11];
    float* out = (float*)d_out;

    const int attn_smem = 6 * 128 * kQStr * 2;   // 110592 bytes
    static int cfg_done = 0;
    cudaFuncSetAttribute(attn_kernel,
                         cudaFuncAttributeMaxDynamicSharedMemorySize, attn_smem);
    (void)cfg_done;

    dim3 blk(256);
    dim3 ggrid(kH / 64, kM / 64);

    gemm_kernel<<<ggrid, blk>>>(q, Wq, bq, nullptr, 0);
    gemm_kernel<<<ggrid, blk>>>(k, Wk, bk, nullptr, 1);
    gemm_kernel<<<ggrid, blk>>>(v, Wv, bv, nullptr, 2);

    attn_kernel<<<dim3(kS / 128, kB * kNH), blk, attn_smem>>>(ab);

    gemm_kernel<<<ggrid, blk>>>(nullptr, Wo, bo, out, 3);
}

// round 3
// speedup vs baseline: 2.9768x; 1.6646x over previous
#include <cuda_runtime.h>
#include <cuda_bf16.h>
#include <cstdint>

// Problem constants
constexpr int kB  = 2;
constexpr int kS  = 2048;
constexpr int kH  = 512;
constexpr int kNH = 8;
constexpr int kDK = 64;
constexpr int kM  = kB * kS;       // 4096
constexpr float kScale = 0.125f;   // 1/sqrt(64)

constexpr int kHE = kB * kNH * kS * kDK;  // elems per head tensor (2M)

// Scratch (device globals; no allocations allowed)
__device__ __nv_bfloat16 g_qhi[kHE], g_qlo[kHE];
__device__ __nv_bfloat16 g_khi[kHE], g_klo[kHE];
__device__ __nv_bfloat16 g_vhi[kHE], g_vlo[kHE];
__device__ float g_ctx[kM * kH];          // [B*S, H]

// ---------------------------------------------------------------------------
// MMA helpers (validated in R2)
// ---------------------------------------------------------------------------
__device__ __forceinline__ uint32_t smaddr(const void* p) {
    return (uint32_t)__cvta_generic_to_shared(p);
}
__device__ __forceinline__ void ldsm_x4(uint32_t* r, uint32_t a) {
    asm volatile("ldmatrix.sync.aligned.m8n8.x4.shared.b16 {%0,%1,%2,%3},[%4];"
        : "=r"(r[0]), "=r"(r[1]), "=r"(r[2]), "=r"(r[3]) : "r"(a));
}
__device__ __forceinline__ void ldsm_x2(uint32_t* r, uint32_t a) {
    asm volatile("ldmatrix.sync.aligned.m8n8.x2.shared.b16 {%0,%1},[%2];"
        : "=r"(r[0]), "=r"(r[1]) : "r"(a));
}
__device__ __forceinline__ void ldsm_x2t(uint32_t* r, uint32_t a) {
    asm volatile("ldmatrix.sync.aligned.m8n8.x2.trans.shared.b16 {%0,%1},[%2];"
        : "=r"(r[0]), "=r"(r[1]) : "r"(a));
}
__device__ __forceinline__ void mma_bf16(float* c, const uint32_t* a,
                                         const uint32_t* b) {
    asm volatile(
        "mma.sync.aligned.m16n8k16.row.col.f32.bf16.bf16.f32 "
        "{%0,%1,%2,%3},{%4,%5,%6,%7},{%8,%9},{%0,%1,%2,%3};"
        : "+f"(c[0]), "+f"(c[1]), "+f"(c[2]), "+f"(c[3])
        : "r"(a[0]), "r"(a[1]), "r"(a[2]), "r"(a[3]), "r"(b[0]), "r"(b[1]));
}
__device__ __forceinline__ uint32_t pack_bf16(float x, float y) {
    __nv_bfloat162 h = __floats2bfloat162_rn(x, y);
    return *reinterpret_cast<uint32_t*>(&h);
}
// split float4 -> hi/lo bf16x2 pairs
__device__ __forceinline__ void split4(float4 v, uint32_t& h0, uint32_t& h1,
                                       uint32_t& l0, uint32_t& l1) {
    __nv_bfloat162 a = __floats2bfloat162_rn(v.x, v.y);
    __nv_bfloat162 b = __floats2bfloat162_rn(v.z, v.w);
    h0 = *reinterpret_cast<uint32_t*>(&a);
    h1 = *reinterpret_cast<uint32_t*>(&b);
    l0 = pack_bf16(v.x - __low2float(a), v.y - __high2float(a));
    l1 = pack_bf16(v.z - __low2float(b), v.w - __high2float(b));
}

// ---------------------------------------------------------------------------
// Tensor-core GEMM core: Y[M=4096, N=512] = X @ W + bias (fp32 in, bf16 hi/lo
// 3-MMA split on tensor cores, fp32 accum).
// CTA 128x128, K-step 32, 8 warps (4 in M x 2 in N), warp tile 32x64.
// mode 0/1/2: head-layout bf16 hi/lo output (mode 0 scaled); mode 3: fp32 out.
// ---------------------------------------------------------------------------
constexpr int kXStr = 40;    // X tile smem stride (bf16 elems)
constexpr int kWStr = 136;   // W tile smem stride

__device__ __forceinline__ void gemm_core(
    const float* __restrict__ X, const float* __restrict__ W,
    const float* __restrict__ bias, float* __restrict__ Yout, int mode)
{
    __shared__ __nv_bfloat16 Xh[128 * kXStr], Xl[128 * kXStr];
    __shared__ __nv_bfloat16 Wh[32 * kWStr],  Wl[32 * kWStr];

    const int tid  = threadIdx.x;
    const int lane = tid & 31, w = tid >> 5;
    const int wm = w >> 1, wn = w & 1;
    const int m0 = blockIdx.y << 7, n0 = blockIdx.x << 7;

    float acc[2][8][4];
#pragma unroll
    for (int mi = 0; mi < 2; ++mi)
#pragma unroll
        for (int jn = 0; jn < 8; ++jn)
#pragma unroll
            for (int i = 0; i < 4; ++i) acc[mi][jn][i] = 0.f;

    // staging indices
    const int xr = tid >> 3, xc = (tid & 7) << 2;     // +p*32 rows
    const int wr = tid >> 5, wc = (tid & 31) << 2;    // +p*8 rows

    float4 xs[4], ws[4];
#pragma unroll
    for (int p = 0; p < 4; ++p) {
        xs[p] = *(const float4*)&X[(size_t)(m0 + xr + (p << 5)) * kH + xc];
        ws[p] = *(const float4*)&W[(size_t)(wr + (p << 3)) * kH + n0 + wc];
    }

    for (int k0 = 0; k0 < kH; k0 += 32) {
        __syncthreads();
#pragma unroll
        for (int p = 0; p < 4; ++p) {
            uint32_t h0, h1, l0, l1;
            split4(xs[p], h0, h1, l0, l1);
            const int xo = (xr + (p << 5)) * kXStr + xc;
            *(uint32_t*)&Xh[xo] = h0; *(uint32_t*)&Xh[xo + 2] = h1;
            *(uint32_t*)&Xl[xo] = l0; *(uint32_t*)&Xl[xo + 2] = l1;
            split4(ws[p], h0, h1, l0, l1);
            const int wo = (wr + (p << 3)) * kWStr + wc;
            *(uint32_t*)&Wh[wo] = h0; *(uint32_t*)&Wh[wo + 2] = h1;
            *(uint32_t*)&Wl[wo] = l0; *(uint32_t*)&Wl[wo + 2] = l1;
        }
        __syncthreads();

        if (k0 + 32 < kH) {
#pragma unroll
            for (int p = 0; p < 4; ++p) {
                xs[p] = *(const float4*)&X[(size_t)(m0 + xr + (p << 5)) * kH + k0 + 32 + xc];
                ws[p] = *(const float4*)&W[(size_t)(k0 + 32 + wr + (p << 3)) * kH + n0 + wc];
            }
        }

#pragma unroll
        for (int k16 = 0; k16 < 2; ++k16) {
            uint32_t afh[2][4], afl[2][4];
#pragma unroll
            for (int mi = 0; mi < 2; ++mi) {
                const int row = (wm << 5) + (mi << 4) + (lane & 15);
                const int col = (k16 << 4) + ((lane >> 4) << 3);
                ldsm_x4(afh[mi], smaddr(&Xh[row * kXStr + col]));
                ldsm_x4(afl[mi], smaddr(&Xl[row * kXStr + col]));
            }
#pragma unroll
            for (int jn = 0; jn < 8; ++jn) {
                const int brow = (k16 << 4) + (lane & 15);
                const int bcol = (wn << 6) + (jn << 3);
                uint32_t bh[2], bl[2];
                ldsm_x2t(bh, smaddr(&Wh[brow * kWStr + bcol]));
                ldsm_x2t(bl, smaddr(&Wl[brow * kWStr + bcol]));
#pragma unroll
                for (int mi = 0; mi < 2; ++mi) {
                    mma_bf16(acc[mi][jn], afh[mi], bh);
                    mma_bf16(acc[mi][jn], afl[mi], bh);
                    mma_bf16(acc[mi][jn], afh[mi], bl);
                }
            }
        }
    }

    // epilogue
    __nv_bfloat16* oh = (mode == 0) ? g_qhi : (mode == 1) ? g_khi : g_vhi;
    __nv_bfloat16* ol = (mode == 0) ? g_qlo : (mode == 1) ? g_klo : g_vlo;

#pragma unroll
    for (int jn = 0; jn < 8; ++jn) {
        const int n = n0 + (wn << 6) + (jn << 3) + ((lane & 3) << 1);
        float2 bv = *(const float2*)&bias[n];
#pragma unroll
        for (int mi = 0; mi < 2; ++mi) {
#pragma unroll
            for (int half = 0; half < 2; ++half) {
                const int m = m0 + (wm << 5) + (mi << 4) + (lane >> 2) + (half << 3);
                float v0 = acc[mi][jn][half * 2 + 0] + bv.x;
                float v1 = acc[mi][jn][half * 2 + 1] + bv.y;
                if (mode == 0) { v0 *= kScale; v1 *= kScale; }
                if (mode < 3) {
                    const int b_ = m >> 11;
                    const int s_ = m & (kS - 1);
                    const int h_ = n >> 6;
                    const int d_ = n & (kDK - 1);
                    size_t off = (((size_t)(b_ * kNH + h_)) * kS + s_) * kDK + d_;
                    __nv_bfloat162 hv = __floats2bfloat162_rn(v0, v1);
                    *(__nv_bfloat162*)&oh[off] = hv;
                    *(uint32_t*)&ol[off] = pack_bf16(v0 - __low2float(hv),
                                                     v1 - __high2float(hv));
                } else {
                    *(float2*)&Yout[(size_t)m * kH + n] = make_float2(v0, v1);
                }
            }
        }
    }
}

__global__ __launch_bounds__(256, 1) void qkv_gemm(
    const float* __restrict__ q, const float* __restrict__ k,
    const float* __restrict__ v,
    const float* __restrict__ Wq, const float* __restrict__ Wk,
    const float* __restrict__ Wv,
    const float* __restrict__ bq, const float* __restrict__ bk,
    const float* __restrict__ bv)
{
    const int mode = blockIdx.z;
    const float* X = (mode == 0) ? q : (mode == 1) ? k : v;
    const float* W = (mode == 0) ? Wq : (mode == 1) ? Wk : Wv;
    const float* B = (mode == 0) ? bq : (mode == 1) ? bk : bv;
    gemm_core(X, W, B, nullptr, mode);
}

__global__ __launch_bounds__(256, 1) void out_gemm(
    const float* __restrict__ Wo, const float* __restrict__ bo,
    float* __restrict__ out)
{
    gemm_core(g_ctx, Wo, bo, out, 3);
}

// ---------------------------------------------------------------------------
// Tensor-core flash attention (unchanged from R2)
// ---------------------------------------------------------------------------
constexpr int kQStr = 72;

__global__ __launch_bounds__(256, 1) void attn_kernel(const float* __restrict__ bias)
{
    extern __shared__ __nv_bfloat16 sm[];
    __nv_bfloat16* Qh = sm;
    __nv_bfloat16* Ql = Qh + 128 * kQStr;
    __nv_bfloat16* Kh = Ql + 128 * kQStr;
    __nv_bfloat16* Kl = Kh + 128 * kQStr;
    __nv_bfloat16* Vh = Kl + 128 * kQStr;
    __nv_bfloat16* Vl = Vh + 128 * kQStr;

    const int bh = blockIdx.y;
    const int q0 = blockIdx.x << 7;
    const int tid = threadIdx.x;
    const int lane = tid & 31, w = tid >> 5;

    const size_t hb = (size_t)bh * kS * kDK;
    const __nv_bfloat16* Qgh = g_qhi + hb;
    const __nv_bfloat16* Qgl = g_qlo + hb;
    const __nv_bfloat16* Kgh = g_khi + hb;
    const __nv_bfloat16* Kgl = g_klo + hb;
    const __nv_bfloat16* Vgh = g_vhi + hb;
    const __nv_bfloat16* Vgl = g_vlo + hb;
    const float* Bp = bias + (size_t)bh * kS * kS + (size_t)q0 * kS;

    {
        const int r = tid >> 3, c8 = (tid & 7) << 3;
#pragma unroll
        for (int u = 0; u < 4; ++u) {
            const int row = r + (u << 5);
            *(uint4*)&Qh[row * kQStr + c8] =
                *(const uint4*)&Qgh[(size_t)(q0 + row) * kDK + c8];
            *(uint4*)&Ql[row * kQStr + c8] =
                *(const uint4*)&Qgl[(size_t)(q0 + row) * kDK + c8];
        }
    }
    __syncthreads();

    uint32_t qfh[4][4], qfl[4][4];
    {
        const int r0 = w << 4;
#pragma unroll
        for (int kc = 0; kc < 4; ++kc) {
            const int row = r0 + (lane & 15);
            const int col = (kc << 4) + ((lane >> 4) << 3);
            ldsm_x4(qfh[kc], smaddr(&Qh[row * kQStr + col]));
            ldsm_x4(qfl[kc], smaddr(&Ql[row * kQStr + col]));
        }
    }

    float O[8][4];
#pragma unroll
    for (int j = 0; j < 8; j++)
#pragma unroll
        for (int i = 0; i < 4; i++) O[j][i] = 0.f;
    float m0 = -1e30f, m1 = -1e30f, l0 = 0.f, l1 = 0.f;

    const int rq = lane >> 2;
    const int cq = (lane & 3) << 1;

    for (int t = 0; t < kS / 128; ++t) {
        const int k0 = t << 7;
        __syncthreads();
        {
            const int r = tid >> 3, c8 = (tid & 7) << 3;
#pragma unroll
            for (int u = 0; u < 4; ++u) {
                const int row = r + (u << 5);
                const size_t g = (size_t)(k0 + row) * kDK + c8;
                *(uint4*)&Kh[row * kQStr + c8] = *(const uint4*)&Kgh[g];
                *(uint4*)&Kl[row * kQStr + c8] = *(const uint4*)&Kgl[g];
                *(uint4*)&Vh[row * kQStr + c8] = *(const uint4*)&Vgh[g];
                *(uint4*)&Vl[row * kQStr + c8] = *(const uint4*)&Vgl[g];
            }
        }
        __syncthreads();

        float acc[16][4];
#pragma unroll
        for (int j = 0; j < 16; ++j) {
            acc[j][0] = acc[j][1] = acc[j][2] = acc[j][3] = 0.f;
#pragma unroll
            for (int kc = 0; kc < 4; ++kc) {
                const int row = (j << 3) + (lane & 7);
                const int col = (kc << 4) + (((lane >> 3) & 1) << 3);
                uint32_t kb[2], kbl[2];
                ldsm_x2(kb, smaddr(&Kh[row * kQStr + col]));
                mma_bf16(acc[j], qfh[kc], kb);
                mma_bf16(acc[j], qfl[kc], kb);
                ldsm_x2(kbl, smaddr(&Kl[row * kQStr + col]));
                mma_bf16(acc[j], qfh[kc], kbl);
            }
            const float* bp = Bp + (size_t)((w << 4) + rq) * kS + k0 + (j << 3) + cq;
            float2 bA = *(const float2*)bp;
            float2 bB = *(const float2*)(bp + 8 * (size_t)kS);
            acc[j][0] += bA.x; acc[j][1] += bA.y;
            acc[j][2] += bB.x; acc[j][3] += bB.y;
        }

        float mx0 = -1e30f, mx1 = -1e30f;
#pragma unroll
        for (int j = 0; j < 16; ++j) {
            mx0 = fmaxf(mx0, fmaxf(acc[j][0], acc[j][1]));
            mx1 = fmaxf(mx1, fmaxf(acc[j][2], acc[j][3]));
        }
        mx0 = fmaxf(mx0, __shfl_xor_sync(0xffffffffu, mx0, 1));
        mx0 = fmaxf(mx0, __shfl_xor_sync(0xffffffffu, mx0, 2));
        mx1 = fmaxf(mx1, __shfl_xor_sync(0xffffffffu, mx1, 1));
        mx1 = fmaxf(mx1, __shfl_xor_sync(0xffffffffu, mx1, 2));

        const float mn0 = fmaxf(m0, mx0), mn1 = fmaxf(m1, mx1);
        const float a0 = __expf(m0 - mn0), a1 = __expf(m1 - mn1);
        m0 = mn0; m1 = mn1;
        l0 *= a0;  l1 *= a1;
#pragma unroll
        for (int jn = 0; jn < 8; ++jn) {
            O[jn][0] *= a0; O[jn][1] *= a0;
            O[jn][2] *= a1; O[jn][3] *= a1;
        }

        uint32_t Ph[8][4], Pl[8][4];
#pragma unroll
        for (int j = 0; j < 16; ++j) {
            float p0 = __expf(acc[j][0] - mn0);
            float p1 = __expf(acc[j][1] - mn0);
            float p2 = __expf(acc[j][2] - mn1);
            float p3 = __expf(acc[j][3] - mn1);
            l0 += p0 + p1;
            l1 += p2 + p3;
            const int kc = j >> 1, bofs = (j & 1) << 1;
            __nv_bfloat162 h01 = __floats2bfloat162_rn(p0, p1);
            __nv_bfloat162 h23 = __floats2bfloat162_rn(p2, p3);
            Ph[kc][bofs]     = *reinterpret_cast<uint32_t*>(&h01);
            Ph[kc][bofs + 1] = *reinterpret_cast<uint32_t*>(&h23);
            Pl[kc][bofs]     = pack_bf16(p0 - __low2float(h01), p1 - __high2float(h01));
            Pl[kc][bofs + 1] = pack_bf16(p2 - __low2float(h23), p3 - __high2float(h23));
        }

#pragma unroll
        for (int jn = 0; jn < 8; ++jn) {
#pragma unroll
            for (int kc = 0; kc < 8; ++kc) {
                const int row = (kc << 4) + (lane & 15);
                const int col = jn << 3;
                uint32_t vb[2], vbl[2];
                ldsm_x2t(vb, smaddr(&Vh[row * kQStr + col]));
                mma_bf16(O[jn], Ph[kc], vb);
                mma_bf16(O[jn], Pl[kc], vb);
                ldsm_x2t(vbl, smaddr(&Vl[row * kQStr + col]));
                mma_bf16(O[jn], Ph[kc], vbl);
            }
        }
    }

    l0 += __shfl_xor_sync(0xffffffffu, l0, 1);
    l0 += __shfl_xor_sync(0xffffffffu, l0, 2);
    l1 += __shfl_xor_sync(0xffffffffu, l1, 1);
    l1 += __shfl_xor_sync(0xffffffffu, l1, 2);
    const float inv0 = 1.f / l0, inv1 = 1.f / l1;

    const int b_ = bh >> 3, h_ = bh & 7;
    const int grow = q0 + (w << 4) + rq;
    float* cp = g_ctx + ((size_t)b_ * kS + grow) * kH + h_ * kDK + cq;
#pragma unroll
    for (int jn = 0; jn < 8; ++jn) {
        *(float2*)(cp + (jn << 3)) =
            make_float2(O[jn][0] * inv0, O[jn][1] * inv0);
        *(float2*)(cp + (jn << 3) + 8 * kH) =
            make_float2(O[jn][2] * inv1, O[jn][3] * inv1);
    }
}

// ---------------------------------------------------------------------------
extern "C" void kernel_launch(void* const* d_in, const int* in_sizes, int n_in,
                              void* d_out, int out_size)
{
    const float* q  = (const float*)d_in[0];
    const float* k  = (const float*)d_in[1];
    const float* v  = (const float*)d_in[2];
    const float* ab = (const float*)d_in[3];
    const float* Wq = (const float*)d_in[4];
    const float* bq = (const float*)d_in[5];
    const float* Wk = (const float*)d_in[6];
    const float* bk = (const float*)d_in[7];
    const float* Wv = (const float*)d_in[8];
    const float* bv = (const float*)d_in[9];
    const float* Wo = (const float*)d_in[10];
    const float* bo = (const float*)d_in[11];
    float* out = (float*)d_out;

    const int attn_smem = 6 * 128 * kQStr * 2;   // 110592 bytes
    cudaFuncSetAttribute(attn_kernel,
                         cudaFuncAttributeMaxDynamicSharedMemorySize, attn_smem);

    dim3 blk(256);
    qkv_gemm<<<dim3(kH / 128, kM / 128, 3), blk>>>(q, k, v, Wq, Wk, Wv, bq, bk, bv);
    attn_kernel<<<dim3(kS / 128, kB * kNH), blk, attn_smem>>>(ab);
    out_gemm<<<dim3(kH / 128, kM / 128), blk>>>(Wo, bo, out);
}

// round 4
// speedup vs baseline: 3.2907x; 1.1054x over previous
#include <cuda_runtime.h>
#include <cuda_bf16.h>
#include <cstdint>

// Problem constants
constexpr int kB  = 2;
constexpr int kS  = 2048;
constexpr int kH  = 512;
constexpr int kNH = 8;
constexpr int kDK = 64;
constexpr int kM  = kB * kS;       // 4096
constexpr float kScale = 0.125f;   // 1/sqrt(64)

constexpr int kHE = kB * kNH * kS * kDK;  // elems per head tensor (2M)

// Scratch (device globals; no allocations allowed)
__device__ __nv_bfloat16 g_qhi[kHE], g_qlo[kHE];
__device__ __nv_bfloat16 g_khi[kHE], g_klo[kHE];
__device__ __nv_bfloat16 g_vhi[kHE], g_vlo[kHE];
__device__ float g_ctx[kM * kH];          // [B*S, H]

// ---------------------------------------------------------------------------
// MMA / async-copy helpers
// ---------------------------------------------------------------------------
__device__ __forceinline__ uint32_t smaddr(const void* p) {
    return (uint32_t)__cvta_generic_to_shared(p);
}
__device__ __forceinline__ void ldsm_x4(uint32_t* r, uint32_t a) {
    asm volatile("ldmatrix.sync.aligned.m8n8.x4.shared.b16 {%0,%1,%2,%3},[%4];"
        : "=r"(r[0]), "=r"(r[1]), "=r"(r[2]), "=r"(r[3]) : "r"(a));
}
__device__ __forceinline__ void ldsm_x4t(uint32_t* r, uint32_t a) {
    asm volatile("ldmatrix.sync.aligned.m8n8.x4.trans.shared.b16 {%0,%1,%2,%3},[%4];"
        : "=r"(r[0]), "=r"(r[1]), "=r"(r[2]), "=r"(r[3]) : "r"(a));
}
__device__ __forceinline__ void ldsm_x2t(uint32_t* r, uint32_t a) {
    asm volatile("ldmatrix.sync.aligned.m8n8.x2.trans.shared.b16 {%0,%1},[%2];"
        : "=r"(r[0]), "=r"(r[1]) : "r"(a));
}
__device__ __forceinline__ void mma_bf16(float* c, const uint32_t* a,
                                         const uint32_t* b) {
    asm volatile(
        "mma.sync.aligned.m16n8k16.row.col.f32.bf16.bf16.f32 "
        "{%0,%1,%2,%3},{%4,%5,%6,%7},{%8,%9},{%0,%1,%2,%3};"
        : "+f"(c[0]), "+f"(c[1]), "+f"(c[2]), "+f"(c[3])
        : "r"(a[0]), "r"(a[1]), "r"(a[2]), "r"(a[3]), "r"(b[0]), "r"(b[1]));
}
__device__ __forceinline__ uint32_t pack_bf16(float x, float y) {
    __nv_bfloat162 h = __floats2bfloat162_rn(x, y);
    return *reinterpret_cast<uint32_t*>(&h);
}
__device__ __forceinline__ void split4(float4 v, uint32_t& h0, uint32_t& h1,
                                       uint32_t& l0, uint32_t& l1) {
    __nv_bfloat162 a = __floats2bfloat162_rn(v.x, v.y);
    __nv_bfloat162 b = __floats2bfloat162_rn(v.z, v.w);
    h0 = *reinterpret_cast<uint32_t*>(&a);
    h1 = *reinterpret_cast<uint32_t*>(&b);
    l0 = pack_bf16(v.x - __low2float(a), v.y - __high2float(a));
    l1 = pack_bf16(v.z - __low2float(b), v.w - __high2float(b));
}
__device__ __forceinline__ void cp16(uint32_t dst, const void* src) {
    asm volatile("cp.async.cg.shared.global [%0],[%1],16;"
        :: "r"(dst), "l"(src));
}
__device__ __forceinline__ void cp_commit() {
    asm volatile("cp.async.commit_group;");
}
template <int N>
__device__ __forceinline__ void cp_wait() {
    asm volatile("cp.async.wait_group %0;" :: "n"(N));
}

// ---------------------------------------------------------------------------
// Tensor-core GEMM (unchanged from R3)
// ---------------------------------------------------------------------------
constexpr int kXStr = 40;
constexpr int kWStr = 136;

__device__ __forceinline__ void ldsm_x4_raw(uint32_t* r, uint32_t a) { ldsm_x4(r, a); }

__device__ __forceinline__ void gemm_core(
    const float* __restrict__ X, const float* __restrict__ W,
    const float* __restrict__ bias, float* __restrict__ Yout, int mode)
{
    __shared__ __nv_bfloat16 Xh[128 * kXStr], Xl[128 * kXStr];
    __shared__ __nv_bfloat16 Wh[32 * kWStr],  Wl[32 * kWStr];

    const int tid  = threadIdx.x;
    const int lane = tid & 31, w = tid >> 5;
    const int wm = w >> 1, wn = w & 1;
    const int m0 = blockIdx.y << 7, n0 = blockIdx.x << 7;

    float acc[2][8][4];
#pragma unroll
    for (int mi = 0; mi < 2; ++mi)
#pragma unroll
        for (int jn = 0; jn < 8; ++jn)
#pragma unroll
            for (int i = 0; i < 4; ++i) acc[mi][jn][i] = 0.f;

    const int xr = tid >> 3, xc = (tid & 7) << 2;
    const int wr = tid >> 5, wc = (tid & 31) << 2;

    float4 xs[4], ws[4];
#pragma unroll
    for (int p = 0; p < 4; ++p) {
        xs[p] = *(const float4*)&X[(size_t)(m0 + xr + (p << 5)) * kH + xc];
        ws[p] = *(const float4*)&W[(size_t)(wr + (p << 3)) * kH + n0 + wc];
    }

    for (int k0 = 0; k0 < kH; k0 += 32) {
        __syncthreads();
#pragma unroll
        for (int p = 0; p < 4; ++p) {
            uint32_t h0, h1, l0, l1;
            split4(xs[p], h0, h1, l0, l1);
            const int xo = (xr + (p << 5)) * kXStr + xc;
            *(uint32_t*)&Xh[xo] = h0; *(uint32_t*)&Xh[xo + 2] = h1;
            *(uint32_t*)&Xl[xo] = l0; *(uint32_t*)&Xl[xo + 2] = l1;
            split4(ws[p], h0, h1, l0, l1);
            const int wo = (wr + (p << 3)) * kWStr + wc;
            *(uint32_t*)&Wh[wo] = h0; *(uint32_t*)&Wh[wo + 2] = h1;
            *(uint32_t*)&Wl[wo] = l0; *(uint32_t*)&Wl[wo + 2] = l1;
        }
        __syncthreads();

        if (k0 + 32 < kH) {
#pragma unroll
            for (int p = 0; p < 4; ++p) {
                xs[p] = *(const float4*)&X[(size_t)(m0 + xr + (p << 5)) * kH + k0 + 32 + xc];
                ws[p] = *(const float4*)&W[(size_t)(k0 + 32 + wr + (p << 3)) * kH + n0 + wc];
            }
        }

#pragma unroll
        for (int k16 = 0; k16 < 2; ++k16) {
            uint32_t afh[2][4], afl[2][4];
#pragma unroll
            for (int mi = 0; mi < 2; ++mi) {
                const int row = (wm << 5) + (mi << 4) + (lane & 15);
                const int col = (k16 << 4) + ((lane >> 4) << 3);
                ldsm_x4(afh[mi], smaddr(&Xh[row * kXStr + col]));
                ldsm_x4(afl[mi], smaddr(&Xl[row * kXStr + col]));
            }
#pragma unroll
            for (int jn = 0; jn < 8; ++jn) {
                const int brow = (k16 << 4) + (lane & 15);
                const int bcol = (wn << 6) + (jn << 3);
                uint32_t bh[2], bl[2];
                ldsm_x2t(bh, smaddr(&Wh[brow * kWStr + bcol]));
                ldsm_x2t(bl, smaddr(&Wl[brow * kWStr + bcol]));
#pragma unroll
                for (int mi = 0; mi < 2; ++mi) {
                    mma_bf16(acc[mi][jn], afh[mi], bh);
                    mma_bf16(acc[mi][jn], afl[mi], bh);
                    mma_bf16(acc[mi][jn], afh[mi], bl);
                }
            }
        }
    }

    __nv_bfloat16* oh = (mode == 0) ? g_qhi : (mode == 1) ? g_khi : g_vhi;
    __nv_bfloat16* ol = (mode == 0) ? g_qlo : (mode == 1) ? g_klo : g_vlo;

#pragma unroll
    for (int jn = 0; jn < 8; ++jn) {
        const int n = n0 + (wn << 6) + (jn << 3) + ((lane & 3) << 1);
        float2 bv = *(const float2*)&bias[n];
#pragma unroll
        for (int mi = 0; mi < 2; ++mi) {
#pragma unroll
            for (int half = 0; half < 2; ++half) {
                const int m = m0 + (wm << 5) + (mi << 4) + (lane >> 2) + (half << 3);
                float v0 = acc[mi][jn][half * 2 + 0] + bv.x;
                float v1 = acc[mi][jn][half * 2 + 1] + bv.y;
                if (mode == 0) { v0 *= kScale; v1 *= kScale; }
                if (mode < 3) {
                    const int b_ = m >> 11;
                    const int s_ = m & (kS - 1);
                    const int h_ = n >> 6;
                    const int d_ = n & (kDK - 1);
                    size_t off = (((size_t)(b_ * kNH + h_)) * kS + s_) * kDK + d_;
                    __nv_bfloat162 hv = __floats2bfloat162_rn(v0, v1);
                    *(__nv_bfloat162*)&oh[off] = hv;
                    *(uint32_t*)&ol[off] = pack_bf16(v0 - __low2float(hv),
                                                     v1 - __high2float(hv));
                } else {
                    *(float2*)&Yout[(size_t)m * kH + n] = make_float2(v0, v1);
                }
            }
        }
    }
}

__global__ __launch_bounds__(256, 1) void qkv_gemm(
    const float* __restrict__ q, const float* __restrict__ k,
    const float* __restrict__ v,
    const float* __restrict__ Wq, const float* __restrict__ Wk,
    const float* __restrict__ Wv,
    const float* __restrict__ bq, const float* __restrict__ bk,
    const float* __restrict__ bv)
{
    const int mode = blockIdx.z;
    const float* X = (mode == 0) ? q : (mode == 1) ? k : v;
    const float* W = (mode == 0) ? Wq : (mode == 1) ? Wk : Wv;
    const float* B = (mode == 0) ? bq : (mode == 1) ? bk : bv;
    gemm_core(X, W, B, nullptr, mode);
}

__global__ __launch_bounds__(256, 1) void out_gemm(
    const float* __restrict__ Wo, const float* __restrict__ bo,
    float* __restrict__ out)
{
    gemm_core(g_ctx, Wo, bo, out, 3);
}

// ---------------------------------------------------------------------------
// Tensor-core flash attention.
// R4: cp.async double-buffered K/V (2 stages) + LDSM.x4 fragment loads.
// smem: Qh,Ql [128][72] + 2 stages x (Kh,Kl,Vh,Vl)[128][72] = 184320 B.
// ---------------------------------------------------------------------------
constexpr int kQStr = 72;
constexpr int kTileE = 128 * kQStr;           // elems per 128x72 tile
constexpr int kStageE = 4 * kTileE;           // K/V stage (4 arrays)

__global__ __launch_bounds__(256, 1) void attn_kernel(const float* __restrict__ bias)
{
    extern __shared__ __nv_bfloat16 sm[];
    __nv_bfloat16* Qh = sm;
    __nv_bfloat16* Ql = Qh + kTileE;
    __nv_bfloat16* KV = Ql + kTileE;          // stage base

    const int bh = blockIdx.y;
    const int q0 = blockIdx.x << 7;
    const int tid = threadIdx.x;
    const int lane = tid & 31, w = tid >> 5;

    const size_t hb = (size_t)bh * kS * kDK;
    const __nv_bfloat16* Qgh = g_qhi + hb;
    const __nv_bfloat16* Qgl = g_qlo + hb;
    const __nv_bfloat16* Kgh = g_khi + hb;
    const __nv_bfloat16* Kgl = g_klo + hb;
    const __nv_bfloat16* Vgh = g_vhi + hb;
    const __nv_bfloat16* Vgl = g_vlo + hb;
    const float* Bp = bias + (size_t)bh * kS * kS + (size_t)q0 * kS;

    const int r = tid >> 3, c8 = (tid & 7) << 3;   // staging indices

    // issue cp.async for K/V tile 0 (stage 0)
    {
        __nv_bfloat16* Kh = KV;
        __nv_bfloat16* Kl = Kh + kTileE;
        __nv_bfloat16* Vh = Kl + kTileE;
        __nv_bfloat16* Vl = Vh + kTileE;
#pragma unroll
        for (int u = 0; u < 4; ++u) {
            const int row = r + (u << 5);
            const size_t g = (size_t)row * kDK + c8;
            const int so = row * kQStr + c8;
            cp16(smaddr(&Kh[so]), &Kgh[g]);
            cp16(smaddr(&Kl[so]), &Kgl[g]);
            cp16(smaddr(&Vh[so]), &Vgh[g]);
            cp16(smaddr(&Vl[so]), &Vgl[g]);
        }
        cp_commit();
    }

    // Load Q tile (plain LDG, once)
#pragma unroll
    for (int u = 0; u < 4; ++u) {
        const int row = r + (u << 5);
        *(uint4*)&Qh[row * kQStr + c8] =
            *(const uint4*)&Qgh[(size_t)(q0 + row) * kDK + c8];
        *(uint4*)&Ql[row * kQStr + c8] =
            *(const uint4*)&Qgl[(size_t)(q0 + row) * kDK + c8];
    }
    __syncthreads();

    // Q fragments (resident)
    uint32_t qfh[4][4], qfl[4][4];
    {
        const int r0 = w << 4;
#pragma unroll
        for (int kc = 0; kc < 4; ++kc) {
            const int row = r0 + (lane & 15);
            const int col = (kc << 4) + ((lane >> 4) << 3);
            ldsm_x4(qfh[kc], smaddr(&Qh[row * kQStr + col]));
            ldsm_x4(qfl[kc], smaddr(&Ql[row * kQStr + col]));
        }
    }

    float O[8][4];
#pragma unroll
    for (int j = 0; j < 8; j++)
#pragma unroll
        for (int i = 0; i < 4; i++) O[j][i] = 0.f;
    float m0 = -1e30f, m1 = -1e30f, l0 = 0.f, l1 = 0.f;

    const int rq = lane >> 2;
    const int cq = (lane & 3) << 1;

    // fragment-load lane offsets (x4 forms)
    const int krow_off = (lane & 7) + ((lane >> 4) << 3);   // K: non-trans x4
    const int kcol_off = ((lane >> 3) & 1) << 3;
    const int vrow_off = lane & 15;                          // V: trans x4
    const int vcol_off = (lane >> 4) << 3;

    for (int t = 0; t < kS / 128; ++t) {
        // issue loads for tile t+1 into the alternate stage
        if (t + 1 < kS / 128) {
            __nv_bfloat16* s = KV + ((t + 1) & 1) * kStageE;
            __nv_bfloat16* Kh = s;
            __nv_bfloat16* Kl = Kh + kTileE;
            __nv_bfloat16* Vh = Kl + kTileE;
            __nv_bfloat16* Vl = Vh + kTileE;
            const int k0n = (t + 1) << 7;
#pragma unroll
            for (int u = 0; u < 4; ++u) {
                const int row = r + (u << 5);
                const size_t g = (size_t)(k0n + row) * kDK + c8;
                const int so = row * kQStr + c8;
                cp16(smaddr(&Kh[so]), &Kgh[g]);
                cp16(smaddr(&Kl[so]), &Kgl[g]);
                cp16(smaddr(&Vh[so]), &Vgh[g]);
                cp16(smaddr(&Vl[so]), &Vgl[g]);
            }
            cp_commit();
            cp_wait<1>();      // tile t complete
        } else {
            cp_wait<0>();
        }
        __syncthreads();       // tile t visible to all warps

        __nv_bfloat16* s = KV + (t & 1) * kStageE;
        const __nv_bfloat16* Kh = s;
        const __nv_bfloat16* Kl = Kh + kTileE;
        const __nv_bfloat16* Vh = Kl + kTileE;
        const __nv_bfloat16* Vl = Vh + kTileE;
        const int k0 = t << 7;

        // scores
        float acc[16][4];
#pragma unroll
        for (int jp = 0; jp < 8; ++jp) {
            float* a0 = acc[2 * jp];
            float* a1 = acc[2 * jp + 1];
            a0[0] = a0[1] = a0[2] = a0[3] = 0.f;
            a1[0] = a1[1] = a1[2] = a1[3] = 0.f;
            const int rowb = (jp << 4) + krow_off;
#pragma unroll
            for (int kc = 0; kc < 4; ++kc) {
                const int col = (kc << 4) + kcol_off;
                uint32_t kb[4], kbl[4];
                ldsm_x4(kb, smaddr(&Kh[rowb * kQStr + col]));
                mma_bf16(a0, qfh[kc], kb);
                mma_bf16(a1, qfh[kc], kb + 2);
                mma_bf16(a0, qfl[kc], kb);
                mma_bf16(a1, qfl[kc], kb + 2);
                ldsm_x4(kbl, smaddr(&Kl[rowb * kQStr + col]));
                mma_bf16(a0, qfh[kc], kbl);
                mma_bf16(a1, qfh[kc], kbl + 2);
            }
            const float* bp = Bp + (size_t)((w << 4) + rq) * kS + k0 + (jp << 4) + cq;
            float2 bA0 = *(const float2*)bp;
            float2 bB0 = *(const float2*)(bp + 8 * (size_t)kS);
            float2 bA1 = *(const float2*)(bp + 8);
            float2 bB1 = *(const float2*)(bp + 8 * (size_t)kS + 8);
            a0[0] += bA0.x; a0[1] += bA0.y; a0[2] += bB0.x; a0[3] += bB0.y;
            a1[0] += bA1.x; a1[1] += bA1.y; a1[2] += bB1.x; a1[3] += bB1.y;
        }

        // online softmax
        float mx0 = -1e30f, mx1 = -1e30f;
#pragma unroll
        for (int j = 0; j < 16; ++j) {
            mx0 = fmaxf(mx0, fmaxf(acc[j][0], acc[j][1]));
            mx1 = fmaxf(mx1, fmaxf(acc[j][2], acc[j][3]));
        }
        mx0 = fmaxf(mx0, __shfl_xor_sync(0xffffffffu, mx0, 1));
        mx0 = fmaxf(mx0, __shfl_xor_sync(0xffffffffu, mx0, 2));
        mx1 = fmaxf(mx1, __shfl_xor_sync(0xffffffffu, mx1, 1));
        mx1 = fmaxf(mx1, __shfl_xor_sync(0xffffffffu, mx1, 2));

        const float mn0 = fmaxf(m0, mx0), mn1 = fmaxf(m1, mx1);
        const float a0s = __expf(m0 - mn0), a1s = __expf(m1 - mn1);
        m0 = mn0; m1 = mn1;
        l0 *= a0s;  l1 *= a1s;
#pragma unroll
        for (int jn = 0; jn < 8; ++jn) {
            O[jn][0] *= a0s; O[jn][1] *= a0s;
            O[jn][2] *= a1s; O[jn][3] *= a1s;
        }

        uint32_t Ph[8][4], Pl[8][4];
#pragma unroll
        for (int j = 0; j < 16; ++j) {
            float p0 = __expf(acc[j][0] - mn0);
            float p1 = __expf(acc[j][1] - mn0);
            float p2 = __expf(acc[j][2] - mn1);
            float p3 = __expf(acc[j][3] - mn1);
            l0 += p0 + p1;
            l1 += p2 + p3;
            const int kc = j >> 1, bofs = (j & 1) << 1;
            __nv_bfloat162 h01 = __floats2bfloat162_rn(p0, p1);
            __nv_bfloat162 h23 = __floats2bfloat162_rn(p2, p3);
            Ph[kc][bofs]     = *reinterpret_cast<uint32_t*>(&h01);
            Ph[kc][bofs + 1] = *reinterpret_cast<uint32_t*>(&h23);
            Pl[kc][bofs]     = pack_bf16(p0 - __low2float(h01), p1 - __high2float(h01));
            Pl[kc][bofs + 1] = pack_bf16(p2 - __low2float(h23), p3 - __high2float(h23));
        }

        // O += P @ V
#pragma unroll
        for (int jp = 0; jp < 4; ++jp) {
            float* o0 = O[2 * jp];
            float* o1 = O[2 * jp + 1];
            const int colb = (jp << 4) + vcol_off;
#pragma unroll
            for (int kc = 0; kc < 8; ++kc) {
                const int rowv = (kc << 4) + vrow_off;
                uint32_t vb[4], vbl[4];
                ldsm_x4t(vb, smaddr(&Vh[rowv * kQStr + colb]));
                mma_bf16(o0, Ph[kc], vb);
                mma_bf16(o1, Ph[kc], vb + 2);
                mma_bf16(o0, Pl[kc], vb);
                mma_bf16(o1, Pl[kc], vb + 2);
                ldsm_x4t(vbl, smaddr(&Vl[rowv * kQStr + colb]));
                mma_bf16(o0, Ph[kc], vbl);
                mma_bf16(o1, Ph[kc], vbl + 2);
            }
        }
        __syncthreads();   // done reading stage t before it is overwritten (t+2)
    }

    // epilogue
    l0 += __shfl_xor_sync(0xffffffffu, l0, 1);
    l0 += __shfl_xor_sync(0xffffffffu, l0, 2);
    l1 += __shfl_xor_sync(0xffffffffu, l1, 1);
    l1 += __shfl_xor_sync(0xffffffffu, l1, 2);
    const float inv0 = 1.f / l0, inv1 = 1.f / l1;

    const int b_ = bh >> 3, h_ = bh & 7;
    const int grow = q0 + (w << 4) + rq;
    float* cp = g_ctx + ((size_t)b_ * kS + grow) * kH + h_ * kDK + cq;
#pragma unroll
    for (int jn = 0; jn < 8; ++jn) {
        *(float2*)(cp + (jn << 3)) =
            make_float2(O[jn][0] * inv0, O[jn][1] * inv0);
        *(float2*)(cp + (jn << 3) + 8 * kH) =
            make_float2(O[jn][2] * inv1, O[jn][3] * inv1);
    }
}

// ---------------------------------------------------------------------------
extern "C" void kernel_launch(void* const* d_in, const int* in_sizes, int n_in,
                              void* d_out, int out_size)
{
    const float* q  = (const float*)d_in[0];
    const float* k  = (const float*)d_in[1];
    const float* v  = (const float*)d_in[2];
    const float* ab = (const float*)d_in[3];
    const float* Wq = (const float*)d_in[4];
    const float* bq = (const float*)d_in[5];
    const float* Wk = (const float*)d_in[6];
    const float* bk = (const float*)d_in[7];
    const float* Wv = (const float*)d_in[8];
    const float* bv = (const float*)d_in[9];
    const float* Wo = (const float*)d_in[10];
    const float* bo = (const float*)d_in[11];
    float* out = (float*)d_out;

    const int attn_smem = (2 * kTileE + 2 * kStageE) * 2;   // 184320 bytes
    cudaFuncSetAttribute(attn_kernel,
                         cudaFuncAttributeMaxDynamicSharedMemorySize, attn_smem);

    dim3 blk(256);
    qkv_gemm<<<dim3(kH / 128, kM / 128, 3), blk>>>(q, k, v, Wq, Wk, Wv, bq, bk, bv);
    attn_kernel<<<dim3(kS / 128, kB * kNH), blk, attn_smem>>>(ab);
    out_gemm<<<dim3(kH / 128, kM / 128), blk>>>(Wo, bo, out);
}